// round 1
// baseline (speedup 1.0000x reference)
#include <cuda_runtime.h>
#include <cstdint>
#include <cstddef>

// ScaledDotProductAttention: B=32, S=2048, D=64, fp32.
//   score = Q@K^T / 8;  score[mask] = -1e9;  attn = softmax(score);  ctx = attn@V
// Outputs (concatenated in d_out): context [B,S,D] then attn [B,S,S].

namespace {
constexpr int B_ = 32, S_ = 2048, D_ = 64;
constexpr int TB = 128;       // q rows per CTA
constexpr int KT = 128;       // k cols per tile
constexpr int TBP = 132;      // padded stride for transposed Q/K tiles
constexpr int PSP = 132;      // padded kk-stride for P tile
constexpr int NTHREADS = 256;
constexpr size_t CTX_ELEMS = (size_t)B_ * S_ * D_;
constexpr int SMEM_FLOATS = 2 * D_ * TBP + KT * D_ + TB * PSP;
constexpr int SMEM_BYTES  = SMEM_FLOATS * 4;  // 167,936 B
}

__device__ float g_inv_rowsum[B_ * S_];

__device__ __forceinline__ unsigned long long pk2(float x, float y) {
    unsigned long long r;
    asm("mov.b64 %0, {%1, %2};" : "=l"(r) : "f"(x), "f"(y));
    return r;
}
__device__ __forceinline__ float2 upk2(unsigned long long v) {
    float2 r;
    asm("mov.b64 {%0, %1}, %2;" : "=f"(r.x), "=f"(r.y) : "l"(v));
    return r;
}
__device__ __forceinline__ void fma2(unsigned long long& c, unsigned long long a,
                                     unsigned long long b) {
    asm("fma.rn.f32x2 %0, %1, %2, %0;" : "+l"(c) : "l"(a), "l"(b));
}

__global__ void __launch_bounds__(NTHREADS)
attn_main(const float* __restrict__ Q, const float* __restrict__ Kg,
          const float* __restrict__ V, const int* __restrict__ M,
          float* __restrict__ ctx, float* __restrict__ attn)
{
    extern __shared__ float smem[];
    float* Qs = smem;                // [D][TBP]  (transposed: Qs[d][q])
    float* Ks = Qs + D_ * TBP;       // [D][TBP]  (transposed: Ks[d][k])
    float* Vs = Ks + D_ * TBP;       // [KT][D]   (natural)
    float* Ps = Vs + KT * D_;        // [TB][PSP] (Ps[q][kk])

    const int b  = blockIdx.y;
    const int q0 = blockIdx.x * TB;
    const int t  = threadIdx.x;
    const int tx = t & 15, ty = t >> 4;
    const int rb = ty * 4;           // rows: rb+rr and 64+rb+rr
    const int cb = tx * 4;           // cols: cb+cc and 64+cb+cc

    // ---- stage Q tile transposed
    {
        const float4* Qg = reinterpret_cast<const float4*>(Q + ((size_t)b * S_ + q0) * D_);
        #pragma unroll
        for (int i = 0; i < 8; i++) {
            int idx = t + i * NTHREADS;      // 0..2047 over [128 rows][16 f4]
            int row = idx >> 4;
            int d0  = (idx & 15) << 2;
            float4 v = Qg[idx];
            Qs[(d0 + 0) * TBP + row] = v.x;
            Qs[(d0 + 1) * TBP + row] = v.y;
            Qs[(d0 + 2) * TBP + row] = v.z;
            Qs[(d0 + 3) * TBP + row] = v.w;
        }
    }

    unsigned long long accC[8][2];   // context accumulators (packed f32x2)
    float rsum[8];
    #pragma unroll
    for (int r = 0; r < 8; r++) { rsum[r] = 0.f; accC[r][0] = 0ull; accC[r][1] = 0ull; }

    for (int kt = 0; kt < S_ / KT; kt++) {
        const int k0 = kt * KT;
        __syncthreads();
        {   // stage K (transposed) and V (natural)
            const float4* Kp = reinterpret_cast<const float4*>(Kg + ((size_t)b * S_ + k0) * D_);
            const float4* Vp = reinterpret_cast<const float4*>(V  + ((size_t)b * S_ + k0) * D_);
            float4* Vs4 = reinterpret_cast<float4*>(Vs);
            #pragma unroll
            for (int i = 0; i < 8; i++) {
                int idx = t + i * NTHREADS;
                int row = idx >> 4;
                int d0  = (idx & 15) << 2;
                float4 v = Kp[idx];
                Ks[(d0 + 0) * TBP + row] = v.x;
                Ks[(d0 + 1) * TBP + row] = v.y;
                Ks[(d0 + 2) * TBP + row] = v.z;
                Ks[(d0 + 3) * TBP + row] = v.w;
                Vs4[idx] = Vp[idx];
            }
        }
        __syncthreads();

        // ---- GEMM1: S[8][8] = Q_tile @ K_tile^T  (packed f32x2 along cols)
        unsigned long long accS[8][4];
        #pragma unroll
        for (int r = 0; r < 8; r++)
            accS[r][0] = accS[r][1] = accS[r][2] = accS[r][3] = 0ull;

        #pragma unroll 4
        for (int d = 0; d < D_; d++) {
            const float4 qa0 = *reinterpret_cast<const float4*>(&Qs[d * TBP + rb]);
            const float4 qa1 = *reinterpret_cast<const float4*>(&Qs[d * TBP + 64 + rb]);
            const float4 kb0 = *reinterpret_cast<const float4*>(&Ks[d * TBP + cb]);
            const float4 kb1 = *reinterpret_cast<const float4*>(&Ks[d * TBP + 64 + cb]);
            unsigned long long b2[4] = { pk2(kb0.x, kb0.y), pk2(kb0.z, kb0.w),
                                         pk2(kb1.x, kb1.y), pk2(kb1.z, kb1.w) };
            float a[8] = { qa0.x, qa0.y, qa0.z, qa0.w, qa1.x, qa1.y, qa1.z, qa1.w };
            #pragma unroll
            for (int r = 0; r < 8; r++) {
                unsigned long long ar = pk2(a[r], a[r]);
                fma2(accS[r][0], ar, b2[0]);
                fma2(accS[r][1], ar, b2[1]);
                fma2(accS[r][2], ar, b2[2]);
                fma2(accS[r][3], ar, b2[3]);
            }
        }

        // ---- mask + exp + write unnormalized attn + stage P tile
        #pragma unroll
        for (int r = 0; r < 8; r++) {
            const int lrow = (r < 4) ? (rb + r) : (64 + rb + r - 4);
            const int grow = q0 + lrow;
            const size_t rowoff = ((size_t)b * S_ + grow) * S_ + k0;
            float2 s01 = upk2(accS[r][0]);
            float2 s23 = upk2(accS[r][1]);
            float2 s45 = upk2(accS[r][2]);
            float2 s67 = upk2(accS[r][3]);
            const int4 m0 = *reinterpret_cast<const int4*>(&M[rowoff + cb]);
            const int4 m1 = *reinterpret_cast<const int4*>(&M[rowoff + 64 + cb]);
            float4 p0, p1;
            p0.x = m0.x ? 0.f : __expf(s01.x * 0.125f);
            p0.y = m0.y ? 0.f : __expf(s01.y * 0.125f);
            p0.z = m0.z ? 0.f : __expf(s23.x * 0.125f);
            p0.w = m0.w ? 0.f : __expf(s23.y * 0.125f);
            p1.x = m1.x ? 0.f : __expf(s45.x * 0.125f);
            p1.y = m1.y ? 0.f : __expf(s45.y * 0.125f);
            p1.z = m1.z ? 0.f : __expf(s67.x * 0.125f);
            p1.w = m1.w ? 0.f : __expf(s67.y * 0.125f);
            rsum[r] += ((p0.x + p0.y) + (p0.z + p0.w)) + ((p1.x + p1.y) + (p1.z + p1.w));
            *reinterpret_cast<float4*>(&attn[rowoff + cb])      = p0;
            *reinterpret_cast<float4*>(&attn[rowoff + 64 + cb]) = p1;
            *reinterpret_cast<float4*>(&Ps[lrow * PSP + cb])      = p0;
            *reinterpret_cast<float4*>(&Ps[lrow * PSP + 64 + cb]) = p1;
        }
        __syncthreads();

        // ---- GEMM2: ctx += P @ V_tile
        #pragma unroll 2
        for (int kk = 0; kk < KT; kk += 4) {
            float4 a4[8];
            #pragma unroll
            for (int r = 0; r < 8; r++) {
                const int lrow = (r < 4) ? (rb + r) : (64 + rb + r - 4);
                a4[r] = *reinterpret_cast<const float4*>(&Ps[lrow * PSP + kk]);
            }
            #pragma unroll
            for (int kkk = 0; kkk < 4; kkk++) {
                float4 vb = *reinterpret_cast<const float4*>(&Vs[(kk + kkk) * D_ + cb]);
                unsigned long long b0 = pk2(vb.x, vb.y);
                unsigned long long b1 = pk2(vb.z, vb.w);
                #pragma unroll
                for (int r = 0; r < 8; r++) {
                    float av = (kkk == 0) ? a4[r].x : (kkk == 1) ? a4[r].y
                             : (kkk == 2) ? a4[r].z : a4[r].w;
                    unsigned long long ap = pk2(av, av);
                    fma2(accC[r][0], ap, b0);
                    fma2(accC[r][1], ap, b1);
                }
            }
        }
    }

    // ---- reduce row sums across tx (lane bits 0..3 = tx within half-warp)
    #pragma unroll
    for (int r = 0; r < 8; r++) {
        float v = rsum[r];
        v += __shfl_xor_sync(0xffffffffu, v, 1);
        v += __shfl_xor_sync(0xffffffffu, v, 2);
        v += __shfl_xor_sync(0xffffffffu, v, 4);
        v += __shfl_xor_sync(0xffffffffu, v, 8);
        rsum[r] = 1.0f / v;   // inverse
    }

    // ---- write inv row sums + normalized context
    #pragma unroll
    for (int r = 0; r < 8; r++) {
        const int lrow = (r < 4) ? (rb + r) : (64 + rb + r - 4);
        const int grow = q0 + lrow;
        if (tx == 0) g_inv_rowsum[b * S_ + grow] = rsum[r];
        float2 c01 = upk2(accC[r][0]);
        float2 c23 = upk2(accC[r][1]);
        float4 o;
        o.x = c01.x * rsum[r]; o.y = c01.y * rsum[r];
        o.z = c23.x * rsum[r]; o.w = c23.y * rsum[r];
        *reinterpret_cast<float4*>(&ctx[((size_t)b * S_ + grow) * D_ + cb]) = o;
    }
}

// Rescale attn by 1/rowsum. One float4 per thread; row = i / 512.
__global__ void __launch_bounds__(256)
attn_normalize(float* __restrict__ attn)
{
    size_t i = (size_t)blockIdx.x * blockDim.x + threadIdx.x;   // float4 index
    float4* a4 = reinterpret_cast<float4*>(attn);
    const float inv = g_inv_rowsum[i >> 9];                     // S/4 = 512 f4 per row
    float4 v = a4[i];
    v.x *= inv; v.y *= inv; v.z *= inv; v.w *= inv;
    a4[i] = v;
}

extern "C" void kernel_launch(void* const* d_in, const int* in_sizes, int n_in,
                              void* d_out, int out_size)
{
    const float* Q = (const float*)d_in[0];
    const float* K = (const float*)d_in[1];
    const float* V = (const float*)d_in[2];
    const int*   M = (const int*)d_in[3];
    float* ctx  = (float*)d_out;
    float* attn = (float*)d_out + CTX_ELEMS;

    cudaFuncSetAttribute(attn_main, cudaFuncAttributeMaxDynamicSharedMemorySize, SMEM_BYTES);

    dim3 grid(S_ / TB, B_);
    attn_main<<<grid, NTHREADS, SMEM_BYTES>>>(Q, K, V, M, ctx, attn);

    const int n4 = (int)((size_t)B_ * S_ * S_ / 4 / 256);       // 131072 blocks
    attn_normalize<<<n4, 256>>>(attn);
}

// round 4
// speedup vs baseline: 2.8356x; 2.8356x over previous
#include <cuda_runtime.h>
#include <cuda_bf16.h>
#include <cstdint>
#include <cstddef>

// ScaledDotProductAttention B=32,S=2048,D=64 fp32 via mma.sync bf16-split.
// out = [context (B,S,D) | attn (B,S,S)] fp32.

namespace {
constexpr int B_ = 32, S_ = 2048, D_ = 64;
constexpr int TQ = 128;            // q rows per CTA
constexpr int TK = 128;            // k cols per tile
constexpr int NT = 256;            // threads (8 warps; warp w owns rows w*16..w*16+15)
constexpr int NKT = S_ / TK;       // 16
constexpr size_t CTX_ELEMS = (size_t)B_ * S_ * D_;

// smem byte offsets: six 16KB tiles (128 rows x 128B), all natural layout
constexpr int SM_QHI = 0;
constexpr int SM_QLO = 16384;
constexpr int SM_KHI = 32768;
constexpr int SM_KLO = 49152;
constexpr int SM_VHI = 65536;
constexpr int SM_VLO = 81920;
constexpr int SMEM_TOTAL = 98304;
}

__device__ float g_inv_rowsum[B_ * S_];

__device__ __forceinline__ uint32_t smem_u32(const void* p) {
    uint32_t a;
    asm("{ .reg .u64 t; cvta.to.shared.u64 t, %1; cvt.u32.u64 %0, t; }" : "=r"(a) : "l"(p));
    return a;
}
// SW128 swizzle on byte offset within a [rows x 128B] tile
__device__ __forceinline__ uint32_t swz(uint32_t off) { return off ^ ((off >> 3) & 0x70); }

__device__ __forceinline__ void mma_bf16(float c[4], uint32_t a0, uint32_t a1,
                                         uint32_t a2, uint32_t a3,
                                         uint32_t b0, uint32_t b1) {
    asm volatile(
        "mma.sync.aligned.m16n8k16.row.col.f32.bf16.bf16.f32 "
        "{%0,%1,%2,%3},{%4,%5,%6,%7},{%8,%9},{%0,%1,%2,%3};"
        : "+f"(c[0]), "+f"(c[1]), "+f"(c[2]), "+f"(c[3])
        : "r"(a0), "r"(a1), "r"(a2), "r"(a3), "r"(b0), "r"(b1));
}
__device__ __forceinline__ void ldmat4(uint32_t r[4], uint32_t addr) {
    asm volatile("ldmatrix.sync.aligned.m8n8.x4.shared.b16 {%0,%1,%2,%3},[%4];"
                 : "=r"(r[0]), "=r"(r[1]), "=r"(r[2]), "=r"(r[3]) : "r"(addr));
}
__device__ __forceinline__ void ldmat4t(uint32_t r[4], uint32_t addr) {
    asm volatile("ldmatrix.sync.aligned.m8n8.x4.trans.shared.b16 {%0,%1,%2,%3},[%4];"
                 : "=r"(r[0]), "=r"(r[1]), "=r"(r[2]), "=r"(r[3]) : "r"(addr));
}

__device__ __forceinline__ void bf_split(float x, uint16_t& h, uint16_t& l) {
    __nv_bfloat16 bh = __float2bfloat16(x);
    float r = x - __bfloat162float(bh);
    h = __bfloat16_as_ushort(bh);
    l = __bfloat16_as_ushort(__float2bfloat16(r));
}

// Stage [128 rows x 64 f32] gmem tile -> two bf16 smem tiles (natural, swizzled)
__device__ __forceinline__ void stage_split(const float* __restrict__ g, char* smem,
                                            int hi_off, int lo_off, int t, float scale) {
    const float4* g4 = reinterpret_cast<const float4*>(g);
    #pragma unroll
    for (int i = 0; i < 8; i++) {
        int idx = t + i * NT;            // 2048 float4s: 128 rows x 16
        int row = idx >> 4;
        int c4  = idx & 15;
        float4 v = g4[idx];
        v.x *= scale; v.y *= scale; v.z *= scale; v.w *= scale;
        uint16_t h0,l0,h1,l1,h2,l2,h3,l3;
        bf_split(v.x,h0,l0); bf_split(v.y,h1,l1); bf_split(v.z,h2,l2); bf_split(v.w,h3,l3);
        uint2 hp = { (uint32_t)h0 | ((uint32_t)h1 << 16), (uint32_t)h2 | ((uint32_t)h3 << 16) };
        uint2 lp = { (uint32_t)l0 | ((uint32_t)l1 << 16), (uint32_t)l2 | ((uint32_t)l3 << 16) };
        uint32_t off = swz((uint32_t)(row * 128 + c4 * 8));
        *reinterpret_cast<uint2*>(smem + hi_off + off) = hp;
        *reinterpret_cast<uint2*>(smem + lo_off + off) = lp;
    }
}

__global__ void __launch_bounds__(NT, 1)
attn_tc(const float* __restrict__ Q, const float* __restrict__ Kg,
        const float* __restrict__ V, const int* __restrict__ M,
        float* __restrict__ ctx, float* __restrict__ attn)
{
    extern __shared__ char smem[];
    const uint32_t sb = smem_u32(smem);
    const int b  = blockIdx.y;
    const int q0 = blockIdx.x * TQ;
    const int t  = threadIdx.x;
    const int w  = t >> 5, l = t & 31;
    const int m0 = w * 16;               // this warp's q-row base
    const int g  = l >> 2, tig = l & 3;  // quad row / col id

    // ---- stage Q (scale folded), load Q fragments, then Q smem is idle
    stage_split(Q + ((size_t)b * S_ + q0) * D_, smem, SM_QHI, SM_QLO, t, 0.125f);
    __syncthreads();

    uint32_t qh[4][4], ql[4][4];
    {
        const int arow = m0 + (l & 15);
        const int acb  = (l >> 4) << 4;
        #pragma unroll
        for (int ks = 0; ks < 4; ks++) {
            uint32_t off = (uint32_t)arow * 128
                         + (((uint32_t)(ks * 32 + acb)) ^ ((uint32_t)(arow & 7) << 4));
            ldmat4(qh[ks], sb + SM_QHI + off);
            ldmat4(ql[ks], sb + SM_QLO + off);
        }
    }

    float cacc[8][4];
    #pragma unroll
    for (int i = 0; i < 8; i++) cacc[i][0] = cacc[i][1] = cacc[i][2] = cacc[i][3] = 0.f;
    float rta = 0.f, rtb = 0.f;

    // row addresses for this thread's two q rows
    const int rowA = q0 + m0 + g;
    const int rowB = rowA + 8;
    const int* mA = M + (size_t)(b * S_ + rowA) * S_;
    const int* mB = M + (size_t)(b * S_ + rowB) * S_;
    float* aA = attn + (size_t)(b * S_ + rowA) * S_;
    float* aB = attn + (size_t)(b * S_ + rowB) * S_;

    for (int kt = 0; kt < NKT; kt++) {
        const int k0 = kt * TK;
        __syncthreads();   // previous iteration's ldmatrix reads done
        stage_split(Kg + ((size_t)b * S_ + k0) * D_, smem, SM_KHI, SM_KLO, t, 1.f);
        stage_split(V  + ((size_t)b * S_ + k0) * D_, smem, SM_VHI, SM_VLO, t, 1.f);
        __syncthreads();

        // ---- GEMM1: S[16x128] = (Qh+Ql)(Kh+Kl)^T, drop lo*lo
        float sacc[16][4];
        #pragma unroll
        for (int i = 0; i < 16; i++) sacc[i][0] = sacc[i][1] = sacc[i][2] = sacc[i][3] = 0.f;

        const int brow = (l & 7) + ((l & 16) ? 8 : 0);
        const int bcb  = (l & 8) ? 16 : 0;
        #pragma unroll
        for (int np = 0; np < 8; np++) {
            uint32_t bh[4][4], bl[4][4];
            #pragma unroll
            for (int ks = 0; ks < 4; ks++) {
                uint32_t off = (uint32_t)(np * 16 + brow) * 128
                             + (((uint32_t)(ks * 32 + bcb)) ^ ((uint32_t)(brow & 7) << 4));
                ldmat4(bh[ks], sb + SM_KHI + off);
                ldmat4(bl[ks], sb + SM_KLO + off);
            }
            #pragma unroll
            for (int ks = 0; ks < 4; ks++) {
                mma_bf16(sacc[2*np],   qh[ks][0],qh[ks][1],qh[ks][2],qh[ks][3], bh[ks][0],bh[ks][1]);
                mma_bf16(sacc[2*np+1], qh[ks][0],qh[ks][1],qh[ks][2],qh[ks][3], bh[ks][2],bh[ks][3]);
                mma_bf16(sacc[2*np],   qh[ks][0],qh[ks][1],qh[ks][2],qh[ks][3], bl[ks][0],bl[ks][1]);
                mma_bf16(sacc[2*np+1], qh[ks][0],qh[ks][1],qh[ks][2],qh[ks][3], bl[ks][2],bl[ks][3]);
                mma_bf16(sacc[2*np],   ql[ks][0],ql[ks][1],ql[ks][2],ql[ks][3], bh[ks][0],bh[ks][1]);
                mma_bf16(sacc[2*np+1], ql[ks][0],ql[ks][1],ql[ks][2],ql[ks][3], bh[ks][2],bh[ks][3]);
            }
        }

        // ---- epilogue: mask + exp + attn STG + rowsum
        float rpa = 0.f, rpb = 0.f;
        #pragma unroll
        for (int nt = 0; nt < 16; nt++) {
            const int col = k0 + nt * 8 + tig * 2;
            const int2 ma = *reinterpret_cast<const int2*>(mA + col);
            const int2 mb = *reinterpret_cast<const int2*>(mB + col);
            float p0 = ma.x ? 0.f : __expf(sacc[nt][0]);
            float p1 = ma.y ? 0.f : __expf(sacc[nt][1]);
            float p2 = mb.x ? 0.f : __expf(sacc[nt][2]);
            float p3 = mb.y ? 0.f : __expf(sacc[nt][3]);
            rpa += p0 + p1; rpb += p2 + p3;
            *reinterpret_cast<float2*>(aA + col) = make_float2(p0, p1);
            *reinterpret_cast<float2*>(aB + col) = make_float2(p2, p3);
            sacc[nt][0] = p0; sacc[nt][1] = p1; sacc[nt][2] = p2; sacc[nt][3] = p3;
        }
        rpa += __shfl_xor_sync(0xffffffffu, rpa, 1);
        rpa += __shfl_xor_sync(0xffffffffu, rpa, 2);
        rpb += __shfl_xor_sync(0xffffffffu, rpb, 1);
        rpb += __shfl_xor_sync(0xffffffffu, rpb, 2);
        rta += rpa; rtb += rpb;

        // ---- pack P (C-frag -> A-frag identity), hi/lo split
        uint32_t phi[8][4], plo[8][4];
        #pragma unroll
        for (int kc = 0; kc < 8; kc++) {
            #pragma unroll
            for (int j = 0; j < 4; j++) {
                const int nt = 2 * kc + (j >> 1);
                const int e0 = (j & 1) * 2, e1 = e0 + 1;
                uint16_t h0,l0,h1,l1;
                bf_split(sacc[nt][e0], h0, l0);
                bf_split(sacc[nt][e1], h1, l1);
                phi[kc][j] = (uint32_t)h0 | ((uint32_t)h1 << 16);
                plo[kc][j] = (uint32_t)l0 | ((uint32_t)l1 << 16);
            }
        }
        // NOTE: frag order must be a0=rowg/k0-7, a1=rowg+8/k0-7, a2=rowg/k8-15, a3=rowg+8/k8-15
        // c-frag: c0,c1=row g; c2,c3=row g+8.  a0<-nt even (c0,c1); a1<-nt even (c2,c3);
        // a2<-nt odd (c0,c1); a3<-nt odd (c2,c3).  j mapping above: j0=(nt even,c0c1),
        // j1=(nt even,c2c3), j2=(nt odd,c0c1), j3=(nt odd,c2c3)  => matches a0..a3.

        // ---- GEMM2: ctx += (Ph+Pl)(Vh+Vl), drop lo*lo; V via ldmatrix.trans
        const int vrow = (l & 7) + ((l & 8) ? 8 : 0);
        const int vcb  = (l & 16) ? 16 : 0;
        #pragma unroll
        for (int kc = 0; kc < 8; kc++) {
            #pragma unroll
            for (int np = 0; np < 4; np++) {
                uint32_t off = (uint32_t)(kc * 16 + vrow) * 128
                             + (((uint32_t)(np * 32 + vcb)) ^ ((uint32_t)(vrow & 7) << 4));
                uint32_t vh[4], vl[4];
                ldmat4t(vh, sb + SM_VHI + off);
                ldmat4t(vl, sb + SM_VLO + off);
                mma_bf16(cacc[2*np],   phi[kc][0],phi[kc][1],phi[kc][2],phi[kc][3], vh[0],vh[1]);
                mma_bf16(cacc[2*np+1], phi[kc][0],phi[kc][1],phi[kc][2],phi[kc][3], vh[2],vh[3]);
                mma_bf16(cacc[2*np],   phi[kc][0],phi[kc][1],phi[kc][2],phi[kc][3], vl[0],vl[1]);
                mma_bf16(cacc[2*np+1], phi[kc][0],phi[kc][1],phi[kc][2],phi[kc][3], vl[2],vl[3]);
                mma_bf16(cacc[2*np],   plo[kc][0],plo[kc][1],plo[kc][2],plo[kc][3], vh[0],vh[1]);
                mma_bf16(cacc[2*np+1], plo[kc][0],plo[kc][1],plo[kc][2],plo[kc][3], vh[2],vh[3]);
            }
        }
    }

    // ---- finalize: normalize ctx, write inv rowsums
    const float inva = 1.0f / rta, invb = 1.0f / rtb;
    if (tig == 0) {
        g_inv_rowsum[b * S_ + rowA] = inva;
        g_inv_rowsum[b * S_ + rowB] = invb;
    }
    float* cA = ctx + (size_t)(b * S_ + rowA) * D_;
    float* cB = ctx + (size_t)(b * S_ + rowB) * D_;
    #pragma unroll
    for (int nt = 0; nt < 8; nt++) {
        const int col = nt * 8 + tig * 2;
        *reinterpret_cast<float2*>(cA + col) = make_float2(cacc[nt][0] * inva, cacc[nt][1] * inva);
        *reinterpret_cast<float2*>(cB + col) = make_float2(cacc[nt][2] * invb, cacc[nt][3] * invb);
    }
}

// Rescale attn by 1/rowsum (memory-bound, ~75% DRAM measured).
__global__ void __launch_bounds__(256)
attn_normalize(float* __restrict__ attn)
{
    size_t i = (size_t)blockIdx.x * blockDim.x + threadIdx.x;   // float4 index
    float4* a4 = reinterpret_cast<float4*>(attn);
    const float inv = g_inv_rowsum[i >> 9];                     // 512 f4 per row
    float4 v = a4[i];
    v.x *= inv; v.y *= inv; v.z *= inv; v.w *= inv;
    a4[i] = v;
}

extern "C" void kernel_launch(void* const* d_in, const int* in_sizes, int n_in,
                              void* d_out, int out_size)
{
    const float* Q = (const float*)d_in[0];
    const float* K = (const float*)d_in[1];
    const float* V = (const float*)d_in[2];
    const int*   M = (const int*)d_in[3];
    float* ctx  = (float*)d_out;
    float* attn = (float*)d_out + CTX_ELEMS;

    cudaFuncSetAttribute(attn_tc, cudaFuncAttributeMaxDynamicSharedMemorySize, SMEM_TOTAL);

    dim3 grid(S_ / TQ, B_);
    attn_tc<<<grid, NT, SMEM_TOTAL>>>(Q, K, V, M, ctx, attn);

    const int n4 = (int)((size_t)B_ * S_ * S_ / 4 / 256);
    attn_normalize<<<n4, 256>>>(attn);
}